// round 3
// baseline (speedup 1.0000x reference)
#include <cuda_runtime.h>
#include <math.h>

#define NB 64
#define NT 512
#define NM 8
#define NV 50
#define TPB 128
#define TILES 2          // NT / (2*TPB)
#define LUTN 1024
#define LUTF 1024.0f

typedef unsigned long long u64;

// Per-module score LUT: entry i = { f(u_i) - M_bound,  f(u_{i+1}) - f(u_i) }
// where u = h/(1+h), f = log2e * (b2 + sum_j w2_j * tanh(h*w1_j + b1_j)).
__device__ float2 g_lut[NM][LUTN];

__device__ __forceinline__ u64 pk2(float x, float y){
  u64 r; asm("mov.b64 %0, {%1,%2};" : "=l"(r) : "f"(x), "f"(y)); return r;
}
__device__ __forceinline__ void up2(u64 v, float &x, float &y){
  asm("mov.b64 {%0,%1}, %2;" : "=f"(x), "=f"(y) : "l"(v));
}
__device__ __forceinline__ u64 ffma2(u64 a, u64 b, u64 c){
  u64 d; asm("fma.rn.f32x2 %0, %1, %2, %3;" : "=l"(d) : "l"(a), "l"(b), "l"(c));
  return d;
}
__device__ __forceinline__ u64 fadd2(u64 a, u64 b){
  u64 d; asm("add.rn.f32x2 %0, %1, %2;" : "=l"(d) : "l"(a), "l"(b));
  return d;
}
__device__ __forceinline__ float ex2f(float x){ float r; asm("ex2.approx.f32 %0, %1;" : "=f"(r) : "f"(x)); return r; }
__device__ __forceinline__ float rcpf(float x){ float r; asm("rcp.approx.f32 %0, %1;" : "=f"(r) : "f"(x)); return r; }

// ---------------- LUT builder (one block per module) ----------------
__global__ void lut_build(const float* __restrict__ w1, const float* __restrict__ b1,
                          const float* __restrict__ w2, const float* __restrict__ b2)
{
  const int m = blockIdx.x;
  const float LOG2E = 1.4426950408889634f;
  float W1[8], B1[8], W2[8];
  float bias = b2[m];
  float M = bias;        // analytic upper bound on the raw score
  float lim = bias;      // h -> inf limit
  #pragma unroll
  for (int j = 0; j < 8; j++){
    W1[j] = w1[m*8+j]; B1[j] = b1[m*8+j]; W2[j] = w2[m*8+j];
    M += fabsf(W2[j]);
    lim += W2[j] * (W1[j] > 0.f ? 1.f : (W1[j] < 0.f ? -1.f : tanhf(B1[j])));
  }
  M   *= LOG2E;
  lim *= LOG2E;

  for (int i = threadIdx.x; i < LUTN; i += blockDim.x){
    float f0, f1;
    {
      float u = (float)i / LUTF;
      float h = u / (1.f - u);
      float s = bias;
      #pragma unroll
      for (int j = 0; j < 8; j++) s += W2[j] * tanhf(fmaf(h, W1[j], B1[j]));
      f0 = s * LOG2E;
    }
    if (i + 1 == LUTN){
      f1 = lim;
    } else {
      float u = (float)(i + 1) / LUTF;
      float h = u / (1.f - u);
      float s = bias;
      #pragma unroll
      for (int j = 0; j < 8; j++) s += W2[j] * tanhf(fmaf(h, W1[j], B1[j]));
      f1 = s * LOG2E;
    }
    g_lut[m][i] = make_float2(f0 - M, f1 - f0);
  }
}

// ---------------- main kernel ----------------
__device__ __forceinline__ void node_update(float g, float A, float C,
                                            const float2* __restrict__ sLUT,
                                            float &l, float &acc)
{
  float h = fmaxf(fmaf(g, A, C), 0.f);
  float r = rcpf(1.f + h);
  float q = fmaf(r, -LUTF, LUTF);        // u * LUTN, u = 1 - 1/(1+h)
  int   i = (int)q;                      // trunc == floor (q >= 0)
  i = min(max(i, 0), LUTN - 1);
  float fr = q - (float)i;
  float2 e = sLUT[i];
  float p = ex2f(fmaf(fr, e.y, e.x));    // exp2(score - bound), in (0,1]
  l += p;
  acc = fmaf(h, p, acc);
}

__global__ void __launch_bounds__(TPB, 8)
ima_kernel(const float* __restrict__ x,  const float* __restrict__ PA,
           const float* __restrict__ conv_w, const float* __restrict__ conv_b,
           const float* __restrict__ bn_gamma, const float* __restrict__ bn_beta,
           const float* __restrict__ bn_mean,  const float* __restrict__ bn_var,
           float* __restrict__ out)
{
  const int blk  = blockIdx.x;           // 0 .. NB*NM*TILES-1
  const int tile = blk & (TILES - 1);
  const int bm   = blk / TILES;
  const int m    = bm & (NM - 1);
  const int b    = bm / NM;

  // PA transposed [w][v-pair], each entry = { {p0,p0}, {p1,p1} } for f32x2 FMA.
  __shared__ ulonglong2 sPA[NV][NV/2];   // 20 KB
  __shared__ float2 sLUT[LUTN];          // 8 KB

  // Coalesced staging: consecutive threads -> consecutive w.
  const float* PAm = PA + m * NV * NV;
  for (int i = threadIdx.x; i < NV * (NV/2); i += TPB){
    int vp = i / NV;            // 0..24
    int w  = i - vp * NV;       // 0..49, contiguous across threads
    float p0 = PAm[(2*vp    ) * NV + w];
    float p1 = PAm[(2*vp + 1) * NV + w];
    ulonglong2 e; e.x = pk2(p0, p0); e.y = pk2(p1, p1);
    sPA[w][vp] = e;
  }
  for (int i = threadIdx.x; i < LUTN; i += TPB)
    sLUT[i] = g_lut[m][i];

  // Fold conv (scalar) + BN (eval): h = relu(fma(agg, A, C))
  const float scale = bn_gamma[m] * rsqrtf(bn_var[m] + 1e-5f);
  const float A = conv_w[m] * scale;
  const float C = (conv_b[m] - bn_mean[m]) * scale + bn_beta[m];
  __syncthreads();

  // Each thread owns two adjacent timesteps t0, t0+1 (packed lanes).
  const int t0 = tile * (2 * TPB) + 2 * threadIdx.x;
  const float* xb = x + ((size_t)(b * NM * NV + m * NV)) * NT + t0;

  u64 xm[NV];
  #pragma unroll
  for (int v = 0; v < NV; v++){
    float2 val = *reinterpret_cast<const float2*>(xb + (size_t)v * NT);
    xm[v] = pk2(val.x, val.y);
  }

  float l0 = 0.f, l1 = 0.f, a0 = 0.f, a1 = 0.f;

  // Two rows per iteration: 4 independent FFMA2 chains + 4 node_updates in flight.
  #pragma unroll 1
  for (int w = 0; w < NV; w += 2){
    const ulonglong2* rowA = sPA[w];
    const ulonglong2* rowB = sPA[w + 1];
    u64 ca0 = 0ULL, ca1 = 0ULL, cb0 = 0ULL, cb1 = 0ULL;
    #pragma unroll
    for (int vp = 0; vp < NV/2; vp++){
      ulonglong2 eA = rowA[vp];
      ulonglong2 eB = rowB[vp];
      ca0 = ffma2(xm[2*vp    ], eA.x, ca0);
      ca1 = ffma2(xm[2*vp + 1], eA.y, ca1);
      cb0 = ffma2(xm[2*vp    ], eB.x, cb0);
      cb1 = ffma2(xm[2*vp + 1], eB.y, cb1);
    }
    float gax, gay, gbx, gby;
    up2(fadd2(ca0, ca1), gax, gay);
    up2(fadd2(cb0, cb1), gbx, gby);

    node_update(gax, A, C, sLUT, l0, a0);
    node_update(gay, A, C, sLUT, l1, a1);
    node_update(gbx, A, C, sLUT, l0, a0);
    node_update(gby, A, C, sLUT, l1, a1);
  }

  float2 o;
  o.x = a0 / l0;
  o.y = a1 / l1;
  *reinterpret_cast<float2*>(out + (size_t)(b * NM + m) * NT + t0) = o;
}

extern "C" void kernel_launch(void* const* d_in, const int* in_sizes, int n_in,
                              void* d_out, int out_size)
{
  (void)in_sizes; (void)n_in; (void)out_size;
  lut_build<<<NM, 256>>>((const float*)d_in[8],  (const float*)d_in[9],
                         (const float*)d_in[10], (const float*)d_in[11]);
  ima_kernel<<<NB * NM * TILES, TPB>>>(
      (const float*)d_in[0],  (const float*)d_in[1],
      (const float*)d_in[2],  (const float*)d_in[3],
      (const float*)d_in[4],  (const float*)d_in[5],
      (const float*)d_in[6],  (const float*)d_in[7],
      (float*)d_out);
}

// round 4
// speedup vs baseline: 2.9739x; 2.9739x over previous
#include <cuda_runtime.h>
#include <math.h>

#define NB 64
#define NT 512
#define NM 8
#define NV 50
#define NVP 25           // v-pairs
#define TPB 128
#define TILES 4          // NT / TPB, one timestep per thread
#define LUTN 1024
#define LUTF 1024.0f

typedef unsigned long long u64;

// Per-module score LUT: entry i = { f(u_i) - M_bound,  f(u_{i+1}) - f(u_i) }
// u = h/(1+h), f = log2e * (b2 + sum_j w2_j * tanh(h*w1_j + b1_j)).
__device__ float2 g_lut[NM][LUTN];

__device__ __forceinline__ u64 pk2(float x, float y){
  u64 r; asm("mov.b64 %0, {%1,%2};" : "=l"(r) : "f"(x), "f"(y)); return r;
}
__device__ __forceinline__ void up2(u64 v, float &x, float &y){
  asm("mov.b64 {%0,%1}, %2;" : "=f"(x), "=f"(y) : "l"(v));
}
__device__ __forceinline__ u64 ffma2(u64 a, u64 b, u64 c){
  u64 d; asm("fma.rn.f32x2 %0, %1, %2, %3;" : "=l"(d) : "l"(a), "l"(b), "l"(c));
  return d;
}
__device__ __forceinline__ u64 fadd2(u64 a, u64 b){
  u64 d; asm("add.rn.f32x2 %0, %1, %2;" : "=l"(d) : "l"(a), "l"(b));
  return d;
}
__device__ __forceinline__ float ex2f(float x){ float r; asm("ex2.approx.f32 %0, %1;" : "=f"(r) : "f"(x)); return r; }
__device__ __forceinline__ float rcpf(float x){ float r; asm("rcp.approx.f32 %0, %1;" : "=f"(r) : "f"(x)); return r; }

// ---------------- LUT builder (one block per module) ----------------
__global__ void lut_build(const float* __restrict__ w1, const float* __restrict__ b1,
                          const float* __restrict__ w2, const float* __restrict__ b2)
{
  const int m = blockIdx.x;
  const float LOG2E = 1.4426950408889634f;
  float W1[8], B1[8], W2[8];
  float bias = b2[m];
  float M = bias;        // analytic upper bound on the raw score
  float lim = bias;      // h -> inf limit
  #pragma unroll
  for (int j = 0; j < 8; j++){
    W1[j] = w1[m*8+j]; B1[j] = b1[m*8+j]; W2[j] = w2[m*8+j];
    M += fabsf(W2[j]);
    lim += W2[j] * (W1[j] > 0.f ? 1.f : (W1[j] < 0.f ? -1.f : tanhf(B1[j])));
  }
  M   *= LOG2E;
  lim *= LOG2E;

  for (int i = threadIdx.x; i < LUTN; i += blockDim.x){
    float f0, f1;
    {
      float u = (float)i / LUTF;
      float h = u / (1.f - u);
      float s = bias;
      #pragma unroll
      for (int j = 0; j < 8; j++) s += W2[j] * tanhf(fmaf(h, W1[j], B1[j]));
      f0 = s * LOG2E;
    }
    if (i + 1 == LUTN){
      f1 = lim;
    } else {
      float u = (float)(i + 1) / LUTF;
      float h = u / (1.f - u);
      float s = bias;
      #pragma unroll
      for (int j = 0; j < 8; j++) s += W2[j] * tanhf(fmaf(h, W1[j], B1[j]));
      f1 = s * LOG2E;
    }
    g_lut[m][i] = make_float2(f0 - M, f1 - f0);
  }
}

// ---------------- main kernel ----------------
__device__ __forceinline__ void node_update(float g, float A, float C,
                                            const float2* __restrict__ sLUT,
                                            float &l, float &acc)
{
  float h = fmaxf(fmaf(g, A, C), 0.f);
  float r = rcpf(1.f + h);
  float q = fmaf(r, -LUTF, LUTF);        // u * LUTN, u = 1 - 1/(1+h)
  int   i = (int)q;                      // trunc == floor (q >= 0)
  i = min(max(i, 0), LUTN - 1);
  float fr = q - (float)i;
  float2 e = sLUT[i];
  float p = ex2f(fmaf(fr, e.y, e.x));    // exp2(score - bound), in (0,1]
  l += p;
  acc = fmaf(h, p, acc);
}

__global__ void __launch_bounds__(TPB)
ima_kernel(const float* __restrict__ x,  const float* __restrict__ PA,
           const float* __restrict__ conv_w, const float* __restrict__ conv_b,
           const float* __restrict__ bn_gamma, const float* __restrict__ bn_beta,
           const float* __restrict__ bn_mean,  const float* __restrict__ bn_var,
           float* __restrict__ out)
{
  const int blk  = blockIdx.x;           // 0 .. NB*NM*TILES-1
  const int tile = blk & (TILES - 1);
  const int bm   = blk / TILES;
  const int m    = bm & (NM - 1);
  const int b    = bm / NM;

  // PA transposed: sPA[w][vp] = { PA[2vp][w], PA[2vp+1][w] }  (v-pairs, no duplication)
  __shared__ u64 sPA[NV][NVP + 1];       // ~10.2 KB (+1 u64 pad per row)
  __shared__ float2 sLUT[LUTN];          // 8 KB

  // Coalesced staging: consecutive threads -> consecutive w.
  const float* PAm = PA + m * NV * NV;
  for (int i = threadIdx.x; i < NV * NVP; i += TPB){
    int vp = i / NV;            // 0..24
    int w  = i - vp * NV;       // 0..49, contiguous across threads
    float p0 = PAm[(2*vp    ) * NV + w];
    float p1 = PAm[(2*vp + 1) * NV + w];
    sPA[w][vp] = pk2(p0, p1);
  }
  for (int i = threadIdx.x; i < LUTN; i += TPB)
    sLUT[i] = g_lut[m][i];

  // Fold conv (scalar) + BN (eval): h = relu(fma(agg, A, C))
  const float scale = bn_gamma[m] * rsqrtf(bn_var[m] + 1e-5f);
  const float A = conv_w[m] * scale;
  const float C = (conv_b[m] - bn_mean[m]) * scale + bn_beta[m];
  __syncthreads();

  // One timestep per thread; x packed over adjacent v (v-pairs).
  const int t = tile * TPB + threadIdx.x;
  const float* xb = x + ((size_t)(b * NM * NV + m * NV)) * NT + t;

  u64 xm[NVP];                            // 50 regs
  #pragma unroll
  for (int vp = 0; vp < NVP; vp++){
    float v0 = xb[(size_t)(2*vp    ) * NT];   // coalesced across threads
    float v1 = xb[(size_t)(2*vp + 1) * NT];
    xm[vp] = pk2(v0, v1);
  }

  float l = 0.f, acc = 0.f;

  // Two rows per iteration: 4 independent FFMA2 chains, 2 node_updates in flight.
  #pragma unroll 1
  for (int w = 0; w < NV; w += 2){
    const u64* rowA = sPA[w];
    const u64* rowB = sPA[w + 1];
    u64 ca0 = 0ULL, ca1 = 0ULL, cb0 = 0ULL, cb1 = 0ULL;
    #pragma unroll
    for (int vp = 0; vp < NVP - 1; vp += 2){
      ca0 = ffma2(xm[vp    ], rowA[vp    ], ca0);
      ca1 = ffma2(xm[vp + 1], rowA[vp + 1], ca1);
      cb0 = ffma2(xm[vp    ], rowB[vp    ], cb0);
      cb1 = ffma2(xm[vp + 1], rowB[vp + 1], cb1);
    }
    ca0 = ffma2(xm[NVP - 1], rowA[NVP - 1], ca0);
    cb0 = ffma2(xm[NVP - 1], rowB[NVP - 1], cb0);

    float ax, ay, bx, by;
    up2(fadd2(ca0, ca1), ax, ay);
    up2(fadd2(cb0, cb1), bx, by);
    node_update(ax + ay, A, C, sLUT, l, acc);
    node_update(bx + by, A, C, sLUT, l, acc);
  }

  out[(size_t)(b * NM + m) * NT + t] = acc / l;
}

extern "C" void kernel_launch(void* const* d_in, const int* in_sizes, int n_in,
                              void* d_out, int out_size)
{
  (void)in_sizes; (void)n_in; (void)out_size;
  lut_build<<<NM, 256>>>((const float*)d_in[8],  (const float*)d_in[9],
                         (const float*)d_in[10], (const float*)d_in[11]);
  ima_kernel<<<NB * NM * TILES, TPB>>>(
      (const float*)d_in[0],  (const float*)d_in[1],
      (const float*)d_in[2],  (const float*)d_in[3],
      (const float*)d_in[4],  (const float*)d_in[5],
      (const float*)d_in[6],  (const float*)d_in[7],
      (float*)d_out);
}

// round 5
// speedup vs baseline: 3.1829x; 1.0703x over previous
#include <cuda_runtime.h>
#include <math.h>

#define NB 64
#define NT 512
#define NM 8
#define NV 50
#define NVP 26           // v-pairs incl. 1 zero-pad pair
#define NQ 13            // quads of 4 v per row
#define TPB 128
#define TILES 4          // NT / TPB, one timestep per thread
#define LUTN 1024
#define LUTF 1024.0f

typedef unsigned long long u64;

// Per-module score LUT: entry i = { f(u_i) - M_bound,  f(u_{i+1}) - f(u_i) }
// u = h/(1+h), f = log2e * (b2 + sum_j w2_j * tanh(h*w1_j + b1_j)).
__device__ float2 g_lut[NM][LUTN];

__device__ __forceinline__ u64 pk2(float x, float y){
  u64 r; asm("mov.b64 %0, {%1,%2};" : "=l"(r) : "f"(x), "f"(y)); return r;
}
__device__ __forceinline__ void up2(u64 v, float &x, float &y){
  asm("mov.b64 {%0,%1}, %2;" : "=f"(x), "=f"(y) : "l"(v));
}
__device__ __forceinline__ u64 ffma2(u64 a, u64 b, u64 c){
  u64 d; asm("fma.rn.f32x2 %0, %1, %2, %3;" : "=l"(d) : "l"(a), "l"(b), "l"(c));
  return d;
}
__device__ __forceinline__ u64 fadd2(u64 a, u64 b){
  u64 d; asm("add.rn.f32x2 %0, %1, %2;" : "=l"(d) : "l"(a), "l"(b));
  return d;
}
__device__ __forceinline__ float ex2f(float x){ float r; asm("ex2.approx.f32 %0, %1;" : "=f"(r) : "f"(x)); return r; }
__device__ __forceinline__ float rcpf(float x){ float r; asm("rcp.approx.f32 %0, %1;" : "=f"(r) : "f"(x)); return r; }

// ---------------- LUT builder (one block per module) ----------------
__global__ void lut_build(const float* __restrict__ w1, const float* __restrict__ b1,
                          const float* __restrict__ w2, const float* __restrict__ b2)
{
  const int m = blockIdx.x;
  const float LOG2E = 1.4426950408889634f;
  float W1[8], B1[8], W2[8];
  float bias = b2[m];
  float M = bias;        // analytic upper bound on the raw score
  float lim = bias;      // h -> inf limit
  #pragma unroll
  for (int j = 0; j < 8; j++){
    W1[j] = w1[m*8+j]; B1[j] = b1[m*8+j]; W2[j] = w2[m*8+j];
    M += fabsf(W2[j]);
    lim += W2[j] * (W1[j] > 0.f ? 1.f : (W1[j] < 0.f ? -1.f : tanhf(B1[j])));
  }
  M   *= LOG2E;
  lim *= LOG2E;

  for (int i = threadIdx.x; i < LUTN; i += blockDim.x){
    float f0, f1;
    {
      float u = (float)i / LUTF;
      float h = u / (1.f - u);
      float s = bias;
      #pragma unroll
      for (int j = 0; j < 8; j++) s += W2[j] * tanhf(fmaf(h, W1[j], B1[j]));
      f0 = s * LOG2E;
    }
    if (i + 1 == LUTN){
      f1 = lim;
    } else {
      float u = (float)(i + 1) / LUTF;
      float h = u / (1.f - u);
      float s = bias;
      #pragma unroll
      for (int j = 0; j < 8; j++) s += W2[j] * tanhf(fmaf(h, W1[j], B1[j]));
      f1 = s * LOG2E;
    }
    g_lut[m][i] = make_float2(f0 - M, f1 - f0);
  }
}

// ---------------- main kernel ----------------
__device__ __forceinline__ void node_update(float g, float A, float C,
                                            const float2* __restrict__ sLUT,
                                            float &l, float &acc)
{
  float h = fmaxf(fmaf(g, A, C), 0.f);
  float r = rcpf(1.f + h);
  float q = fmaf(r, -LUTF, LUTF);        // u * LUTN, u = 1 - 1/(1+h)
  int   i = (int)q;                      // trunc == floor (q >= 0)
  i = min(max(i, 0), LUTN - 1);
  float fr = q - (float)i;
  float2 e = sLUT[i];
  float p = ex2f(fmaf(fr, e.y, e.x));    // exp2(score - bound), in (0,1]
  l += p;
  acc = fmaf(h, p, acc);
}

__global__ void __launch_bounds__(TPB)
ima_kernel(const float* __restrict__ x,  const float* __restrict__ PA,
           const float* __restrict__ conv_w, const float* __restrict__ conv_b,
           const float* __restrict__ bn_gamma, const float* __restrict__ bn_beta,
           const float* __restrict__ bn_mean,  const float* __restrict__ bn_var,
           float* __restrict__ out)
{
  const int blk  = blockIdx.x;           // 0 .. NB*NM*TILES-1
  const int tile = blk & (TILES - 1);
  const int bm   = blk / TILES;
  const int m    = bm & (NM - 1);
  const int b    = bm / NM;

  // PA transposed, v-quads: sPA[w][q] = { {PA[4q][w],PA[4q+1][w]}, {PA[4q+2][w],PA[4q+3][w]} }
  __shared__ ulonglong2 sPA[NV][NQ];     // 50*13*16 = 10.4 KB
  __shared__ float2 sLUT[LUTN];          // 8 KB

  // Coalesced staging: consecutive threads -> consecutive w.
  const float* PAm = PA + m * NV * NV;
  for (int i = threadIdx.x; i < NV * NQ; i += TPB){
    int q = i / NV;             // 0..12
    int w = i - q * NV;         // 0..49, contiguous across threads
    int v0 = 4 * q;
    float p0 = PAm[(v0    ) * NV + w];
    float p1 = PAm[(v0 + 1) * NV + w];
    float p2 = (v0 + 2 < NV) ? PAm[(v0 + 2) * NV + w] : 0.f;
    float p3 = (v0 + 3 < NV) ? PAm[(v0 + 3) * NV + w] : 0.f;
    ulonglong2 e; e.x = pk2(p0, p1); e.y = pk2(p2, p3);
    sPA[w][q] = e;
  }
  for (int i = threadIdx.x; i < LUTN; i += TPB)
    sLUT[i] = g_lut[m][i];

  // Fold conv (scalar) + BN (eval): h = relu(fma(agg, A, C))
  const float scale = bn_gamma[m] * rsqrtf(bn_var[m] + 1e-5f);
  const float A = conv_w[m] * scale;
  const float C = (conv_b[m] - bn_mean[m]) * scale + bn_beta[m];
  __syncthreads();

  // One timestep per thread; x packed over adjacent v (v-pairs), padded to 52.
  const int t = tile * TPB + threadIdx.x;
  const float* xb = x + ((size_t)(b * NM * NV + m * NV)) * NT + t;

  u64 xm[NVP];                            // 52 regs
  #pragma unroll
  for (int vp = 0; vp < NV/2; vp++){
    float v0 = xb[(size_t)(2*vp    ) * NT];   // coalesced across threads
    float v1 = xb[(size_t)(2*vp + 1) * NT];
    xm[vp] = pk2(v0, v1);
  }
  xm[NVP - 1] = 0ULL;                     // pad pair (PA pad is zero anyway)

  float l = 0.f, acc = 0.f;

  // Two rows per iteration: 4 independent FFMA2 chains, 2 node_updates in flight.
  // Each LDS.128 broadcast feeds two FFMA2s.
  #pragma unroll 1
  for (int w = 0; w < NV; w += 2){
    const ulonglong2* rowA = sPA[w];
    const ulonglong2* rowB = sPA[w + 1];
    u64 ca0 = 0ULL, ca1 = 0ULL, cb0 = 0ULL, cb1 = 0ULL;
    #pragma unroll
    for (int q = 0; q < NQ; q++){
      ulonglong2 eA = rowA[q];
      ulonglong2 eB = rowB[q];
      ca0 = ffma2(xm[2*q    ], eA.x, ca0);
      ca1 = ffma2(xm[2*q + 1], eA.y, ca1);
      cb0 = ffma2(xm[2*q    ], eB.x, cb0);
      cb1 = ffma2(xm[2*q + 1], eB.y, cb1);
    }
    float ax, ay, bx, by;
    up2(fadd2(ca0, ca1), ax, ay);
    up2(fadd2(cb0, cb1), bx, by);
    node_update(ax + ay, A, C, sLUT, l, acc);
    node_update(bx + by, A, C, sLUT, l, acc);
  }

  out[(size_t)(b * NM + m) * NT + t] = acc / l;
}

extern "C" void kernel_launch(void* const* d_in, const int* in_sizes, int n_in,
                              void* d_out, int out_size)
{
  (void)in_sizes; (void)n_in; (void)out_size;
  lut_build<<<NM, 256>>>((const float*)d_in[8],  (const float*)d_in[9],
                         (const float*)d_in[10], (const float*)d_in[11]);
  ima_kernel<<<NB * NM * TILES, TPB>>>(
      (const float*)d_in[0],  (const float*)d_in[1],
      (const float*)d_in[2],  (const float*)d_in[3],
      (const float*)d_in[4],  (const float*)d_in[5],
      (const float*)d_in[6],  (const float*)d_in[7],
      (float*)d_out);
}

// round 6
// speedup vs baseline: 3.6748x; 1.1545x over previous
#include <cuda_runtime.h>
#include <math.h>

#define NB 64
#define NT 512
#define NM 8
#define NV 50
#define NVP 26           // v-pairs incl. 1 zero-pad pair
#define NQ 13            // quads of 4 v per row
#define TPB 128
#define TILES 2          // each block: 256 timesteps, 2 per thread
#define LUTN 1024
#define LUTF 1024.0f

typedef unsigned long long u64;

// Per-module score LUT: entry i = { f(u_i) - M_bound,  f(u_{i+1}) - f(u_i) }
// u = h/(1+h), f = log2e * (b2 + sum_j w2_j * tanh(h*w1_j + b1_j)).
__device__ float2 g_lut[NM][LUTN];

__device__ __forceinline__ u64 pk2(float x, float y){
  u64 r; asm("mov.b64 %0, {%1,%2};" : "=l"(r) : "f"(x), "f"(y)); return r;
}
__device__ __forceinline__ void up2(u64 v, float &x, float &y){
  asm("mov.b64 {%0,%1}, %2;" : "=f"(x), "=f"(y) : "l"(v));
}
__device__ __forceinline__ u64 ffma2(u64 a, u64 b, u64 c){
  u64 d; asm("fma.rn.f32x2 %0, %1, %2, %3;" : "=l"(d) : "l"(a), "l"(b), "l"(c));
  return d;
}
__device__ __forceinline__ u64 fadd2(u64 a, u64 b){
  u64 d; asm("add.rn.f32x2 %0, %1, %2;" : "=l"(d) : "l"(a), "l"(b));
  return d;
}
__device__ __forceinline__ float ex2f(float x){ float r; asm("ex2.approx.f32 %0, %1;" : "=f"(r) : "f"(x)); return r; }
__device__ __forceinline__ float rcpf(float x){ float r; asm("rcp.approx.f32 %0, %1;" : "=f"(r) : "f"(x)); return r; }

// ---------------- LUT builder (one block per module) ----------------
__global__ void lut_build(const float* __restrict__ w1, const float* __restrict__ b1,
                          const float* __restrict__ w2, const float* __restrict__ b2)
{
  const int m = blockIdx.x;
  const float LOG2E = 1.4426950408889634f;
  float W1[8], B1[8], W2[8];
  float bias = b2[m];
  float M = bias;        // analytic upper bound on the raw score
  float lim = bias;      // h -> inf limit
  #pragma unroll
  for (int j = 0; j < 8; j++){
    W1[j] = w1[m*8+j]; B1[j] = b1[m*8+j]; W2[j] = w2[m*8+j];
    M += fabsf(W2[j]);
    lim += W2[j] * (W1[j] > 0.f ? 1.f : (W1[j] < 0.f ? -1.f : tanhf(B1[j])));
  }
  M   *= LOG2E;
  lim *= LOG2E;

  for (int i = threadIdx.x; i < LUTN; i += blockDim.x){
    float f0, f1;
    {
      float u = (float)i / LUTF;
      float h = u / (1.f - u);
      float s = bias;
      #pragma unroll
      for (int j = 0; j < 8; j++) s += W2[j] * tanhf(fmaf(h, W1[j], B1[j]));
      f0 = s * LOG2E;
    }
    if (i + 1 == LUTN){
      f1 = lim;
    } else {
      float u = (float)(i + 1) / LUTF;
      float h = u / (1.f - u);
      float s = bias;
      #pragma unroll
      for (int j = 0; j < 8; j++) s += W2[j] * tanhf(fmaf(h, W1[j], B1[j]));
      f1 = s * LOG2E;
    }
    g_lut[m][i] = make_float2(f0 - M, f1 - f0);
  }
}

// ---------------- main kernel ----------------
__device__ __forceinline__ void node_update(float g, float A, float C,
                                            const float2* __restrict__ sLUT,
                                            float &l, float &acc)
{
  float h = fmaxf(fmaf(g, A, C), 0.f);
  float r = rcpf(1.f + h);
  float q = fmaf(r, -LUTF, LUTF);        // u * LUTN, u = 1 - 1/(1+h)
  int   i = (int)q;                      // trunc == floor (q >= 0)
  i = min(max(i, 0), LUTN - 1);
  float fr = q - (float)i;
  float2 e = sLUT[i];
  float p = ex2f(fmaf(fr, e.y, e.x));    // exp2(score - bound), in (0,1]
  l += p;
  acc = fmaf(h, p, acc);
}

__global__ void __launch_bounds__(TPB)
ima_kernel(const float* __restrict__ x,  const float* __restrict__ PA,
           const float* __restrict__ conv_w, const float* __restrict__ conv_b,
           const float* __restrict__ bn_gamma, const float* __restrict__ bn_beta,
           const float* __restrict__ bn_mean,  const float* __restrict__ bn_var,
           float* __restrict__ out)
{
  const int blk  = blockIdx.x;           // 0 .. NB*NM*TILES-1
  const int tile = blk & (TILES - 1);
  const int bm   = blk / TILES;
  const int m    = bm & (NM - 1);
  const int b    = bm / NM;

  // PA transposed, v-quads: sPA[w][q] = { {PA[4q][w],PA[4q+1][w]}, {PA[4q+2][w],PA[4q+3][w]} }
  __shared__ ulonglong2 sPA[NV][NQ];     // 10.4 KB
  __shared__ float2 sLUT[LUTN];          // 8 KB

  // Coalesced staging: consecutive threads -> consecutive w.
  const float* PAm = PA + m * NV * NV;
  for (int i = threadIdx.x; i < NV * NQ; i += TPB){
    int q = i / NV;             // 0..12
    int w = i - q * NV;         // 0..49, contiguous across threads
    int v0 = 4 * q;
    float p0 = PAm[(v0    ) * NV + w];
    float p1 = PAm[(v0 + 1) * NV + w];
    float p2 = (v0 + 2 < NV) ? PAm[(v0 + 2) * NV + w] : 0.f;
    float p3 = (v0 + 3 < NV) ? PAm[(v0 + 3) * NV + w] : 0.f;
    ulonglong2 e; e.x = pk2(p0, p1); e.y = pk2(p2, p3);
    sPA[w][q] = e;
  }
  for (int i = threadIdx.x; i < LUTN; i += TPB)
    sLUT[i] = g_lut[m][i];

  // Fold conv (scalar) + BN (eval): h = relu(fma(agg, A, C))
  const float scale = bn_gamma[m] * rsqrtf(bn_var[m] + 1e-5f);
  const float A = conv_w[m] * scale;
  const float C = (conv_b[m] - bn_mean[m]) * scale + bn_beta[m];
  __syncthreads();

  // Two timesteps per thread: ta = base + tid, tb = ta + TPB (both coalesced).
  const int ta = tile * (2 * TPB) + threadIdx.x;
  const float* xbase = x + ((size_t)(b * NM * NV + m * NV)) * NT + ta;

  u64 xa[NVP], xb[NVP];                  // 104 regs total
  #pragma unroll
  for (int vp = 0; vp < NV/2; vp++){
    const float* p0 = xbase + (size_t)(2*vp    ) * NT;
    const float* p1 = xbase + (size_t)(2*vp + 1) * NT;
    xa[vp] = pk2(p0[0],   p1[0]);
    xb[vp] = pk2(p0[TPB], p1[TPB]);
  }
  xa[NVP - 1] = 0ULL;
  xb[NVP - 1] = 0ULL;

  float la = 0.f, aa = 0.f, lb = 0.f, ab = 0.f;

  // Two rows per iteration; each LDS.128 quad feeds 8 FFMA2 (2 rows x 2 timesteps).
  #pragma unroll 1
  for (int w = 0; w < NV; w += 2){
    const ulonglong2* rowA = sPA[w];
    const ulonglong2* rowB = sPA[w + 1];
    u64 aA0 = 0ULL, aA1 = 0ULL, aB0 = 0ULL, aB1 = 0ULL;   // timestep a
    u64 bA0 = 0ULL, bA1 = 0ULL, bB0 = 0ULL, bB1 = 0ULL;   // timestep b
    #pragma unroll
    for (int q = 0; q < NQ; q++){
      ulonglong2 eA = rowA[q];
      ulonglong2 eB = rowB[q];
      aA0 = ffma2(xa[2*q    ], eA.x, aA0);
      aA1 = ffma2(xa[2*q + 1], eA.y, aA1);
      aB0 = ffma2(xa[2*q    ], eB.x, aB0);
      aB1 = ffma2(xa[2*q + 1], eB.y, aB1);
      bA0 = ffma2(xb[2*q    ], eA.x, bA0);
      bA1 = ffma2(xb[2*q + 1], eA.y, bA1);
      bB0 = ffma2(xb[2*q    ], eB.x, bB0);
      bB1 = ffma2(xb[2*q + 1], eB.y, bB1);
    }
    float x0, x1, y0, y1;
    up2(fadd2(aA0, aA1), x0, x1);
    node_update(x0 + x1, A, C, sLUT, la, aa);
    up2(fadd2(aB0, aB1), y0, y1);
    node_update(y0 + y1, A, C, sLUT, la, aa);
    up2(fadd2(bA0, bA1), x0, x1);
    node_update(x0 + x1, A, C, sLUT, lb, ab);
    up2(fadd2(bB0, bB1), y0, y1);
    node_update(y0 + y1, A, C, sLUT, lb, ab);
  }

  float* ob = out + (size_t)(b * NM + m) * NT + ta;
  ob[0]   = aa / la;
  ob[TPB] = ab / lb;
}

extern "C" void kernel_launch(void* const* d_in, const int* in_sizes, int n_in,
                              void* d_out, int out_size)
{
  (void)in_sizes; (void)n_in; (void)out_size;
  lut_build<<<NM, 256>>>((const float*)d_in[8],  (const float*)d_in[9],
                         (const float*)d_in[10], (const float*)d_in[11]);
  ima_kernel<<<NB * NM * TILES, TPB>>>(
      (const float*)d_in[0],  (const float*)d_in[1],
      (const float*)d_in[2],  (const float*)d_in[3],
      (const float*)d_in[4],  (const float*)d_in[5],
      (const float*)d_in[6],  (const float*)d_in[7],
      (float*)d_out);
}